// round 3
// baseline (speedup 1.0000x reference)
#include <cuda_runtime.h>

#define MAXN   16384
#define TPB    256
#define IPT    4      // i-values per thread, held in registers
#define JTILE  256    // j-values per shared tile (== TPB for 1-load-per-thread)
#define JGRID  32     // grid.y replicas striding over j-tiles

// Device-global scratch (no allocations allowed)
__device__ unsigned int g_M;
__device__ unsigned long long g_C, g_T;
__device__ float g_yc[MAXN];
__device__ float g_yhc[MAXN];

__device__ __forceinline__ float pos_inf() { return __int_as_float(0x7f800000); }
__device__ __forceinline__ float neg_inf() { return __int_as_float(0xff800000); }

__global__ void init_kernel() {
    g_M = 0u;
    g_C = 0ull;
    g_T = 0ull;
}

// Compact (y, y_hat) of status==1 items into g_yc/g_yhc. Order is atomic-
// nondeterministic, but all downstream uses are order-invariant sums.
__global__ void compact_kernel(const float* __restrict__ y,
                               const float* __restrict__ yh,
                               const int* __restrict__ status, int n) {
    int i = blockIdx.x * blockDim.x + threadIdx.x;
    if (i < n && status[i] == 1) {
        unsigned int idx = atomicAdd(&g_M, 1u);
        g_yc[idx]  = y[i];
        g_yhc[idx] = yh[i];
    }
}

// Ordered-pair counting:
//   g_T += sum over all i, all compacted j of  (y[i]  >= yc[j])
//   g_C += sum over all i, all compacted j of  (y[i]  >= yc[j]) & (yh[i] >= yhc[j])
// Diagonal (i==j, status_i==1) contributes exactly M to both; subtracted in finalize.
__global__ void __launch_bounds__(TPB)
pair_kernel(const float* __restrict__ y, const float* __restrict__ yh, int n) {
    __shared__ float sy[JTILE];
    __shared__ float syh[JTILE];

    const int M   = (int)g_M;          // written by compact_kernel (prior launch)
    const int tid = threadIdx.x;
    const int ibase = blockIdx.x * (TPB * IPT) + tid;

    // Register-resident i values; out-of-range i -> -inf so every compare is false.
    float yi[IPT], yhi[IPT];
#pragma unroll
    for (int k = 0; k < IPT; k++) {
        int i = ibase + k * TPB;
        bool v = (i < n);
        yi[k]  = v ? y[i]  : neg_inf();
        yhi[k] = v ? yh[i] : neg_inf();
    }

    unsigned int t = 0u, c = 0u;
    const int jtiles = (M + JTILE - 1) / JTILE;

    for (int jt = (int)blockIdx.y; jt < jtiles; jt += (int)gridDim.y) {
        __syncthreads();   // protect previous tile's readers
        int j = jt * JTILE + tid;
        bool v = (j < M);
        sy[tid]  = v ? g_yc[j]  : pos_inf();   // +inf pad -> compares false
        syh[tid] = v ? g_yhc[j] : pos_inf();
        __syncthreads();

#pragma unroll 8
        for (int jj = 0; jj < JTILE; jj++) {
            float yj  = sy[jj];    // warp-broadcast LDS (conflict-free)
            float yhj = syh[jj];
#pragma unroll
            for (int k = 0; k < IPT; k++) {
                unsigned int p1 = (yi[k]  >= yj);
                unsigned int p2 = (yhi[k] >= yhj);
                t += p1;
                c += (p1 & p2);
            }
        }
    }

    // warp reduce then one atomic per warp per counter
#pragma unroll
    for (int off = 16; off; off >>= 1) {
        t += __shfl_down_sync(0xffffffffu, t, off);
        c += __shfl_down_sync(0xffffffffu, c, off);
    }
    if ((tid & 31) == 0) {
        atomicAdd(&g_T, (unsigned long long)t);
        atomicAdd(&g_C, (unsigned long long)c);
    }
}

__global__ void finalize_kernel(float* __restrict__ out) {
    double M = (double)g_M;
    double c = (double)g_C - M;
    double t = (double)g_T - M;
    out[0] = (float)(c / t);
}

extern "C" void kernel_launch(void* const* d_in, const int* in_sizes, int n_in,
                              void* d_out, int out_size) {
    const float* y      = (const float*)d_in[0];
    const float* yh     = (const float*)d_in[1];
    const int*   status = (const int*)d_in[2];
    int n = in_sizes[0];

    init_kernel<<<1, 1>>>();
    compact_kernel<<<(n + TPB - 1) / TPB, TPB>>>(y, yh, status, n);

    int itiles = (n + TPB * IPT - 1) / (TPB * IPT);
    dim3 grid(itiles, JGRID);
    pair_kernel<<<grid, TPB>>>(y, yh, n);

    finalize_kernel<<<1, 1>>>((float*)d_out);
}

// round 4
// speedup vs baseline: 1.0164x; 1.0164x over previous
#include <cuda_runtime.h>

#define TPB   256
#define IPT   4          // i-values per thread (registers)
#define JCH   256        // j-chunk width in original index space
#define NWARP (TPB / 32)

// Device-global accumulators. Statically zero for the very first (correctness)
// call; the finalizing block of each launch resets them for the next replay,
// so every graph replay sees the same initial state (deterministic).
__device__ unsigned long long g_C = 0ull;
__device__ unsigned long long g_T = 0ull;
__device__ unsigned int g_M = 0u;
__device__ unsigned int g_done = 0u;

__device__ __forceinline__ float neg_inf() { return __int_as_float(0xff800000); }

// One fused kernel:
//  - each block locally compacts its 256-wide j-chunk (status==1) into shared
//  - counts ordered pairs: T += (y_i >= yc_j), C += (y_i >= yc_j)&(yh_i >= yhc_j)
//  - block reduction -> 2 global atomics -> fenced done-counter
//  - last block finalizes out[0] = (C - M) / (T - M) and resets state
__global__ void __launch_bounds__(TPB, 8)
cindex_fused_kernel(const float* __restrict__ y,
                    const float* __restrict__ yh,
                    const int* __restrict__ status,
                    int n, float* __restrict__ out, int nblocks) {
    __shared__ float sy[JCH];
    __shared__ float syh[JCH];
    __shared__ unsigned int swcnt[NWARP];
    __shared__ unsigned long long sred[NWARP];
    __shared__ unsigned int s_mj;

    const int tid = threadIdx.x;
    const int wid = tid >> 5;
    const int lid = tid & 31;

    // ---- local compaction of this block's j-chunk ----
    const int j = (int)blockIdx.y * JCH + tid;
    const bool jv = (j < n);
    float yj  = jv ? y[j]  : 0.0f;
    float yhj = jv ? yh[j] : 0.0f;
    const bool keep = jv && (status[j] == 1);

    unsigned int bal = __ballot_sync(0xffffffffu, keep);
    unsigned int pre = __popc(bal & ((1u << lid) - 1u));
    if (lid == 0) swcnt[wid] = __popc(bal);
    __syncthreads();

    unsigned int base = 0;
#pragma unroll
    for (int w = 0; w < NWARP; w++) base += (w < wid) ? swcnt[w] : 0u;
    if (tid == 0) {
        unsigned int m = 0;
#pragma unroll
        for (int w = 0; w < NWARP; w++) m += swcnt[w];
        s_mj = m;
    }
    if (keep) { sy[base + pre] = yj; syh[base + pre] = yhj; }
    __syncthreads();
    const int mj = (int)s_mj;

    // M counted once per j-chunk (only the blockIdx.x == 0 column adds it)
    if (blockIdx.x == 0 && tid == 0 && mj > 0)
        atomicAdd(&g_M, (unsigned int)mj);

    // ---- i values register-resident; out-of-range -> -inf (compares false) ----
    const int ibase = (int)blockIdx.x * (TPB * IPT) + tid;
    float yi[IPT], yhi[IPT];
#pragma unroll
    for (int k = 0; k < IPT; k++) {
        int i = ibase + k * TPB;
        bool v = (i < n);
        yi[k]  = v ? y[i]  : neg_inf();
        yhi[k] = v ? yh[i] : neg_inf();
    }

    // ---- pair counting mainloop ----
    unsigned int tcnt = 0u, ccnt = 0u;
#pragma unroll 4
    for (int jj = 0; jj < mj; jj++) {
        float a = sy[jj];     // warp-broadcast LDS
        float b = syh[jj];
#pragma unroll
        for (int k = 0; k < IPT; k++) {
            unsigned int p1 = (yi[k]  >= a);
            unsigned int p2 = (yhi[k] >= b);
            tcnt += p1;
            ccnt += (p1 & p2);
        }
    }

    // ---- warp reduce, pack (t<<32 | c): per-block c <= 2^18, no carry ----
#pragma unroll
    for (int off = 16; off; off >>= 1) {
        tcnt += __shfl_down_sync(0xffffffffu, tcnt, off);
        ccnt += __shfl_down_sync(0xffffffffu, ccnt, off);
    }
    if (lid == 0)
        sred[wid] = ((unsigned long long)tcnt << 32) | (unsigned long long)ccnt;
    __syncthreads();

    if (tid == 0) {
        unsigned long long s = 0ull;
#pragma unroll
        for (int w = 0; w < NWARP; w++) s += sred[w];
        atomicAdd(&g_T, s >> 32);
        atomicAdd(&g_C, s & 0xffffffffull);
        __threadfence();
        unsigned int old = atomicAdd(&g_done, 1u);
        if (old == (unsigned int)(nblocks - 1)) {
            // all blocks' C/T adds are release-ordered before their done-adds
            __threadfence();
            double M = (double)atomicAdd(&g_M, 0u);
            double c = (double)atomicAdd(&g_C, 0ull) - M;  // drop diagonal
            double t = (double)atomicAdd(&g_T, 0ull) - M;
            out[0] = (float)(c / t);
            // reset for next graph replay
            g_C = 0ull; g_T = 0ull; g_M = 0u; g_done = 0u;
        }
    }
}

extern "C" void kernel_launch(void* const* d_in, const int* in_sizes, int n_in,
                              void* d_out, int out_size) {
    const float* y      = (const float*)d_in[0];
    const float* yh     = (const float*)d_in[1];
    const int*   status = (const int*)d_in[2];
    int n = in_sizes[0];

    int itiles = (n + TPB * IPT - 1) / (TPB * IPT);   // 16 for N=16384
    int jtiles = (n + JCH - 1) / JCH;                 // 64 for N=16384
    dim3 grid(itiles, jtiles);
    cindex_fused_kernel<<<grid, TPB>>>(y, yh, status, n, (float*)d_out,
                                       itiles * jtiles);
}

// round 7
// speedup vs baseline: 1.4855x; 1.4614x over previous
#include <cuda_runtime.h>

#define TPB   256
#define IPT   4          // i-values per thread (registers)
#define JCH   256        // j-chunk width in original index space
#define NWARP (TPB / 32)

// Device-global accumulators. Statically zero for the very first (correctness)
// call; the finalizing block of each launch resets them for the next replay,
// so every graph replay sees the same initial state (deterministic).
__device__ unsigned long long g_C = 0ull;
__device__ unsigned long long g_T = 0ull;
__device__ unsigned int g_M = 0u;
__device__ unsigned int g_done = 0u;

__device__ __forceinline__ float neg_inf() { return __int_as_float(0xff800000); }

// Minimal 4-op pair update:
//   setp.ge.f32      p1, yi, a
//   setp.ge.and.f32  p2, yhi, b, p1
//   @p1 add t; @p2 add c
__device__ __forceinline__ void pair_update(unsigned int& t, unsigned int& c,
                                            float yi, float yhi,
                                            float a, float b) {
    asm volatile(
        "{\n\t"
        ".reg .pred p1, p2;\n\t"
        "setp.ge.f32 p1, %2, %4;\n\t"
        "setp.ge.and.f32 p2, %3, %5, p1;\n\t"
        "@p1 add.u32 %0, %0, 1;\n\t"
        "@p2 add.u32 %1, %1, 1;\n\t"
        "}"
        : "+r"(t), "+r"(c)
        : "f"(yi), "f"(yhi), "f"(a), "f"(b));
}

__global__ void __launch_bounds__(TPB, 8)
cindex_fused_kernel(const float* __restrict__ y,
                    const float* __restrict__ yh,
                    const int* __restrict__ status,
                    int n, float* __restrict__ out, int nblocks) {
    __shared__ float2 sj[JCH];                 // (y, yh) packed -> one LDS.64
    __shared__ unsigned int swcnt[NWARP];
    __shared__ unsigned long long sred[NWARP];
    __shared__ unsigned int s_mj;

    const int tid = threadIdx.x;
    const int wid = tid >> 5;
    const int lid = tid & 31;

    // ---- local compaction of this block's j-chunk (status==1) ----
    const int j = (int)blockIdx.y * JCH + tid;
    const bool jv = (j < n);
    float yj  = jv ? y[j]  : 0.0f;
    float yhj = jv ? yh[j] : 0.0f;
    const bool keep = jv && (status[j] == 1);

    unsigned int bal = __ballot_sync(0xffffffffu, keep);
    unsigned int pre = __popc(bal & ((1u << lid) - 1u));
    if (lid == 0) swcnt[wid] = __popc(bal);
    __syncthreads();

    unsigned int base = 0;
#pragma unroll
    for (int w = 0; w < NWARP; w++) base += (w < wid) ? swcnt[w] : 0u;
    if (tid == 0) {
        unsigned int m = 0;
#pragma unroll
        for (int w = 0; w < NWARP; w++) m += swcnt[w];
        s_mj = m;
    }
    if (keep) sj[base + pre] = make_float2(yj, yhj);
    __syncthreads();
    const int mj = (int)s_mj;

    // M counted once per j-chunk (only the blockIdx.x == 0 column adds it)
    if (blockIdx.x == 0 && tid == 0 && mj > 0)
        atomicAdd(&g_M, (unsigned int)mj);

    // ---- i values register-resident; out-of-range -> -inf (compares false) ----
    const int ibase = (int)blockIdx.x * (TPB * IPT) + tid;
    float yi[IPT], yhi[IPT];
#pragma unroll
    for (int k = 0; k < IPT; k++) {
        int i = ibase + k * TPB;
        bool v = (i < n);
        yi[k]  = v ? y[i]  : neg_inf();
        yhi[k] = v ? yh[i] : neg_inf();
    }

    // ---- pair counting mainloop: 1 LDS.64 + 16 predicate-ops per 4 pairs ----
    unsigned int tcnt = 0u, ccnt = 0u;
#pragma unroll 4
    for (int jj = 0; jj < mj; jj++) {
        float2 ab = sj[jj];    // warp-broadcast LDS.64 (conflict-free)
#pragma unroll
        for (int k = 0; k < IPT; k++)
            pair_update(tcnt, ccnt, yi[k], yhi[k], ab.x, ab.y);
    }

    // ---- warp reduce, pack (t<<32 | c): per-block c <= 2^18, no carry ----
#pragma unroll
    for (int off = 16; off; off >>= 1) {
        tcnt += __shfl_down_sync(0xffffffffu, tcnt, off);
        ccnt += __shfl_down_sync(0xffffffffu, ccnt, off);
    }
    if (lid == 0)
        sred[wid] = ((unsigned long long)tcnt << 32) | (unsigned long long)ccnt;
    __syncthreads();

    if (tid == 0) {
        unsigned long long s = 0ull;
#pragma unroll
        for (int w = 0; w < NWARP; w++) s += sred[w];
        atomicAdd(&g_T, s >> 32);
        atomicAdd(&g_C, s & 0xffffffffull);
        __threadfence();
        unsigned int old = atomicAdd(&g_done, 1u);
        if (old == (unsigned int)(nblocks - 1)) {
            __threadfence();
            double M = (double)atomicAdd(&g_M, 0u);
            double c = (double)atomicAdd(&g_C, 0ull) - M;  // drop diagonal
            double t = (double)atomicAdd(&g_T, 0ull) - M;
            out[0] = (float)(c / t);
            // reset for next graph replay
            g_C = 0ull; g_T = 0ull; g_M = 0u; g_done = 0u;
        }
    }
}

extern "C" void kernel_launch(void* const* d_in, const int* in_sizes, int n_in,
                              void* d_out, int out_size) {
    const float* y      = (const float*)d_in[0];
    const float* yh     = (const float*)d_in[1];
    const int*   status = (const int*)d_in[2];
    int n = in_sizes[0];

    int itiles = (n + TPB * IPT - 1) / (TPB * IPT);   // 16 for N=16384
    int jtiles = (n + JCH - 1) / JCH;                 // 64 for N=16384
    dim3 grid(itiles, jtiles);
    cindex_fused_kernel<<<grid, TPB>>>(y, yh, status, n, (float*)d_out,
                                       itiles * jtiles);
}